// round 8
// baseline (speedup 1.0000x reference)
#include <cuda_runtime.h>
#include <cuda_fp16.h>
#include <cstdint>

#define MAXN 100000
#define CAP 128            // per-node CSR bucket capacity (P(overflow) ~ 0)

// Scratch (__device__ globals; allocation-free rule)
__device__ __align__(16) __half g_A[MAXN * 64]; // h' (fp16, 128B/row = 1 line)
__device__ __align__(16) float  g_B[MAXN * 64]; // aggregation output (fp32)
__device__ int g_cnt[MAXN];                     // in-degree (no self loop)
__device__ __align__(16) int g_csr[MAXN * CAP]; // src row BYTE offsets (s<<7)

// ---------------------------------------------------------------------------
// prep
// ---------------------------------------------------------------------------
__global__ void zero_k(int N) {
    int i = blockIdx.x * blockDim.x + threadIdx.x;
    if (i < N) g_cnt[i] = 0;
}

__global__ void fill_k(const int* __restrict__ ei, int E, int N) {
    int e = blockIdx.x * blockDim.x + threadIdx.x;
    if (e >= E) return;
    int s = __ldg(ei + e);
    int d = __ldg(ei + (size_t)E + e);
    if ((unsigned)s >= (unsigned)N) s = 0;
    if ((unsigned)d >= (unsigned)N) d = 0;
    int pos = atomicAdd(&g_cnt[d], 1);
    if (pos < CAP) g_csr[(size_t)d * CAP + pos] = s << 7;  // byte offset of row
}

// ---------------------------------------------------------------------------
// output store helpers
// ---------------------------------------------------------------------------
__device__ __forceinline__ void store_out(float* p, float v)  { *p = v; }
__device__ __forceinline__ void store_out(__half* p, float v) { *p = __float2half_rn(v); }

// ---------------------------------------------------------------------------
// GEMM: out[N,NOUT] = f(in[N,64]) @ W[64,NOUT] (*dinv[row]) (+postb)
// ---------------------------------------------------------------------------
template <int NOUT, bool PRE, bool POST, bool SCALE, typename OT>
__global__ void __launch_bounds__(256) gemm64_k(
        const float* __restrict__ in, const float* __restrict__ W,
        const float* __restrict__ preb, const float* __restrict__ postb,
        OT* __restrict__ out, int N) {
    constexpr int CPT = NOUT / 16;
    __shared__ float xs[64][65];
    __shared__ __align__(16) float Ws[64 * NOUT];

    const int t = threadIdx.x;
    const int row0 = blockIdx.x * 64;

    #pragma unroll
    for (int i = t; i < 64 * NOUT; i += 256) Ws[i] = W[i];

    #pragma unroll
    for (int i = 0; i < 16; i++) {
        int lin = t + i * 256;
        int r = lin >> 6, c = lin & 63;
        int gr = row0 + r;
        float v = (gr < N) ? in[(size_t)gr * 64 + c] : 0.0f;
        if (PRE) v = fmaxf(v + preb[c], 0.0f);
        xs[r][c] = v;
    }
    __syncthreads();

    const int r0 = (t >> 4) * 4;
    const int c0 = (t & 15) * CPT;

    float acc[4][CPT];
    #pragma unroll
    for (int i = 0; i < 4; i++)
        #pragma unroll
        for (int j = 0; j < CPT; j++) acc[i][j] = 0.0f;

    #pragma unroll
    for (int k = 0; k < 64; k++) {
        float wv[CPT];
        #pragma unroll
        for (int j = 0; j < CPT; j++) wv[j] = Ws[k * NOUT + c0 + j];
        #pragma unroll
        for (int i = 0; i < 4; i++) {
            float a = xs[r0 + i][k];
            #pragma unroll
            for (int j = 0; j < CPT; j++)
                acc[i][j] = fmaf(a, wv[j], acc[i][j]);
        }
    }

    #pragma unroll
    for (int i = 0; i < 4; i++) {
        int gr = row0 + r0 + i;
        if (gr < N) {
            float sc = 1.0f;
            if (SCALE) sc = rsqrtf((float)g_cnt[gr] + 1.0f);
            #pragma unroll
            for (int j = 0; j < CPT; j++) {
                float v = acc[i][j];
                if (SCALE) v *= sc;
                if (POST) v += postb[c0 + j];
                store_out(out + (size_t)gr * NOUT + c0 + j, v);
            }
        }
    }
}

// ---------------------------------------------------------------------------
// Aggregation: warp per node, quarter-warp per edge row.
// 8 lanes x LDG.128 read one 128B fp16 row; 4 groups -> 4 edges per warp
// instruction. fp32 accumulate; shfl-xor fold; fp32 output.
// ---------------------------------------------------------------------------
__device__ __forceinline__ void add8(float* acc, uint4 v) {
    float2 f;
    f = __half22float2(*reinterpret_cast<__half2*>(&v.x)); acc[0] += f.x; acc[1] += f.y;
    f = __half22float2(*reinterpret_cast<__half2*>(&v.y)); acc[2] += f.x; acc[3] += f.y;
    f = __half22float2(*reinterpret_cast<__half2*>(&v.z)); acc[4] += f.x; acc[5] += f.y;
    f = __half22float2(*reinterpret_cast<__half2*>(&v.w)); acc[6] += f.x; acc[7] += f.y;
}

__global__ void __launch_bounds__(256) agg_k(float* __restrict__ outb, int N) {
    int warp = (blockIdx.x * blockDim.x + threadIdx.x) >> 5;
    int lane = threadIdx.x & 31;
    if (warp >= N) return;
    int q = lane & 7;          // lane within group: owns cols [8q, 8q+8)
    int g = lane >> 3;         // group 0..3: edges e ≡ g (mod 4)

    const char* __restrict__ hbase = reinterpret_cast<const char*>(g_A) + q * 16;
    const int*  __restrict__ row   = g_csr + (size_t)warp * CAP;
    int cnt = g_cnt[warp];
    if (cnt > CAP) cnt = CAP;

    float acc[8] = {0, 0, 0, 0, 0, 0, 0, 0};

    // self-loop row: group 0 only
    if (g == 0) {
        uint4 v = *reinterpret_cast<const uint4*>(hbase + (size_t)warp * 128);
        add8(acc, v);
    }

    int e = g;
    for (; e + 4 < cnt; e += 8) {                // 2 gathers in flight
        int off0 = row[e];
        int off1 = row[e + 4];
        uint4 v0 = *reinterpret_cast<const uint4*>(hbase + off0);
        uint4 v1 = *reinterpret_cast<const uint4*>(hbase + off1);
        add8(acc, v0);
        add8(acc, v1);
    }
    if (e < cnt) {
        uint4 v = *reinterpret_cast<const uint4*>(hbase + row[e]);
        add8(acc, v);
    }

    // fold the 4 groups
    #pragma unroll
    for (int i = 0; i < 8; i++) {
        acc[i] += __shfl_xor_sync(0xffffffffu, acc[i], 8);
        acc[i] += __shfl_xor_sync(0xffffffffu, acc[i], 16);
    }

    float di = rsqrtf((float)g_cnt[warp] + 1.0f);
    if (g < 2) {   // groups 0,1 write the 64-float row as 16x STG.128
        float4 w = make_float4(acc[g * 4 + 0] * di, acc[g * 4 + 1] * di,
                               acc[g * 4 + 2] * di, acc[g * 4 + 3] * di);
        *reinterpret_cast<float4*>(outb + (size_t)warp * 64 + q * 8 + g * 4) = w;
    }
}

// ---------------------------------------------------------------------------
// launch
// ---------------------------------------------------------------------------
extern "C" void kernel_launch(void* const* d_in, const int* in_sizes, int n_in,
                              void* d_out, int out_size) {
    const float* x  = (const float*)d_in[0];
    const int*   ei = (const int*)d_in[1];
    const float* W1 = (const float*)d_in[2];
    const float* b1 = (const float*)d_in[3];
    const float* W2 = (const float*)d_in[4];
    const float* b2 = (const float*)d_in[5];
    const float* Wf = (const float*)d_in[6];
    const float* bf = (const float*)d_in[7];
    float* out = (float*)d_out;

    const int N = in_sizes[0] / 64;
    const int E = in_sizes[1] / 2;

    __half* pA = nullptr;
    float*  pB = nullptr;
    cudaGetSymbolAddress((void**)&pA, g_A);
    cudaGetSymbolAddress((void**)&pB, g_B);

    const int T = 256;
    dim3 bn((N + T - 1) / T), be((E + T - 1) / T);
    dim3 bg((N + 63) / 64);
    dim3 bagg((N * 32 + T - 1) / T);

    zero_k<<<bn, T>>>(N);
    fill_k<<<be, T>>>(ei, E, N);

    gemm64_k<64, false, false, true, __half><<<bg, T>>>(x, W1, nullptr, nullptr, pA, N);
    agg_k<<<bagg, T>>>(pB, N);

    gemm64_k<64, true, false, true, __half><<<bg, T>>>(pB, W2, b1, nullptr, pA, N);
    agg_k<<<bagg, T>>>(pB, N);

    gemm64_k<32, true, true, false, float><<<bg, T>>>(pB, Wf, b2, bf, out, N);
}

// round 9
// speedup vs baseline: 1.0404x; 1.0404x over previous
#include <cuda_runtime.h>
#include <cuda_fp16.h>
#include <cstdint>

#define MAXN 100000
#define CAP 128            // per-node CSR bucket capacity, multiple of 16
#define ZOFF (MAXN << 7)   // byte offset of the permanently-zero h' row

// Scratch (__device__ globals; allocation-free rule)
// g_A has one extra row (index MAXN): BSS-zeroed, never written -> stays zero.
__device__ __align__(16) __half g_A[(MAXN + 1) * 64];
__device__ __align__(16) float  g_B[MAXN * 64];
__device__ int g_cnt[MAXN];
__device__ __align__(16) int g_csr[MAXN * CAP];  // src row BYTE offsets (s<<7)

// ---------------------------------------------------------------------------
// prep
// ---------------------------------------------------------------------------
__global__ void zero_k(int N) {
    int i = blockIdx.x * blockDim.x + threadIdx.x;
    if (i < N) g_cnt[i] = 0;
}

__global__ void fill_k(const int* __restrict__ ei, int E, int N) {
    int e = blockIdx.x * blockDim.x + threadIdx.x;
    if (e >= E) return;
    int s = __ldg(ei + e);
    int d = __ldg(ei + (size_t)E + e);
    if ((unsigned)s >= (unsigned)N) s = 0;
    if ((unsigned)d >= (unsigned)N) d = 0;
    int pos = atomicAdd(&g_cnt[d], 1);
    if (pos < CAP) g_csr[(size_t)d * CAP + pos] = s << 7;
}

// pad each CSR row to a multiple of 16 with offsets to the zero row
__global__ void pad_k(int N) {
    int i = blockIdx.x * blockDim.x + threadIdx.x;
    if (i >= N) return;
    int c = g_cnt[i];
    if (c > CAP) c = CAP;
    int end = (c + 15) & ~15;
    int* row = g_csr + (size_t)i * CAP;
    for (int j = c; j < end; j++) row[j] = ZOFF;
}

// ---------------------------------------------------------------------------
// GEMM: out[N,NOUT] = f(in[N,64]) @ W[64,NOUT] (*dinv[row]) (+postb)
// ---------------------------------------------------------------------------
template <int NOUT, bool PRE, bool POST, bool SCALE, typename OT>
__global__ void __launch_bounds__(256) gemm64_k(
        const float* __restrict__ in, const float* __restrict__ W,
        const float* __restrict__ preb, const float* __restrict__ postb,
        OT* __restrict__ out, int N) {
    constexpr int CPT = NOUT / 16;
    __shared__ float xs[64][65];
    __shared__ __align__(16) float Ws[64 * NOUT];

    const int t = threadIdx.x;
    const int row0 = blockIdx.x * 64;

    #pragma unroll
    for (int i = t; i < 64 * NOUT; i += 256) Ws[i] = W[i];

    #pragma unroll
    for (int i = 0; i < 16; i++) {
        int lin = t + i * 256;
        int r = lin >> 6, c = lin & 63;
        int gr = row0 + r;
        float v = (gr < N) ? in[(size_t)gr * 64 + c] : 0.0f;
        if (PRE) v = fmaxf(v + preb[c], 0.0f);
        xs[r][c] = v;
    }
    __syncthreads();

    const int r0 = (t >> 4) * 4;
    const int c0 = (t & 15) * CPT;

    float acc[4][CPT];
    #pragma unroll
    for (int i = 0; i < 4; i++)
        #pragma unroll
        for (int j = 0; j < CPT; j++) acc[i][j] = 0.0f;

    #pragma unroll
    for (int k = 0; k < 64; k++) {
        float wv[CPT];
        #pragma unroll
        for (int j = 0; j < CPT; j++) wv[j] = Ws[k * NOUT + c0 + j];
        #pragma unroll
        for (int i = 0; i < 4; i++) {
            float a = xs[r0 + i][k];
            #pragma unroll
            for (int j = 0; j < CPT; j++)
                acc[i][j] = fmaf(a, wv[j], acc[i][j]);
        }
    }

    #pragma unroll
    for (int i = 0; i < 4; i++) {
        int gr = row0 + r0 + i;
        if (gr < N) {
            float sc = 1.0f;
            if (SCALE) sc = rsqrtf((float)g_cnt[gr] + 1.0f);
            float v[CPT];
            #pragma unroll
            for (int j = 0; j < CPT; j++) {
                v[j] = acc[i][j];
                if (SCALE) v[j] *= sc;
                if (POST) v[j] += postb[c0 + j];
            }
            if constexpr (sizeof(OT) == 2 && (CPT % 2) == 0) {
                // packed half2 stores
                #pragma unroll
                for (int j = 0; j < CPT; j += 2) {
                    __half2 h2 = __floats2half2_rn(v[j], v[j + 1]);
                    *reinterpret_cast<__half2*>(
                        reinterpret_cast<__half*>(out) + (size_t)gr * NOUT + c0 + j) = h2;
                }
            } else {
                #pragma unroll
                for (int j = 0; j < CPT; j++)
                    out[(size_t)gr * NOUT + c0 + j] = (OT)v[j];
            }
        }
    }
}

// ---------------------------------------------------------------------------
// Aggregation: warp per node, quarter-warp gathers, fp16 4-edge tree.
// Groups g=0..3, lanes q=0..7 own cols [8q,8q+8). Each iteration covers 16
// edges: group g reads idx int4 at row[b+4g], gathers 4 fp16 rows, tree-sums
// them in fp16 (__hadd2), converts once to fp32 accumulators.
// ---------------------------------------------------------------------------
__device__ __forceinline__ uint4 hadd2_u4(uint4 a, uint4 b) {
    uint4 r;
    *reinterpret_cast<__half2*>(&r.x) = __hadd2(*reinterpret_cast<__half2*>(&a.x),
                                                *reinterpret_cast<__half2*>(&b.x));
    *reinterpret_cast<__half2*>(&r.y) = __hadd2(*reinterpret_cast<__half2*>(&a.y),
                                                *reinterpret_cast<__half2*>(&b.y));
    *reinterpret_cast<__half2*>(&r.z) = __hadd2(*reinterpret_cast<__half2*>(&a.z),
                                                *reinterpret_cast<__half2*>(&b.z));
    *reinterpret_cast<__half2*>(&r.w) = __hadd2(*reinterpret_cast<__half2*>(&a.w),
                                                *reinterpret_cast<__half2*>(&b.w));
    return r;
}

__device__ __forceinline__ void addf32_u4(float* acc, uint4 v) {
    float2 f;
    f = __half22float2(*reinterpret_cast<__half2*>(&v.x)); acc[0] += f.x; acc[1] += f.y;
    f = __half22float2(*reinterpret_cast<__half2*>(&v.y)); acc[2] += f.x; acc[3] += f.y;
    f = __half22float2(*reinterpret_cast<__half2*>(&v.z)); acc[4] += f.x; acc[5] += f.y;
    f = __half22float2(*reinterpret_cast<__half2*>(&v.w)); acc[6] += f.x; acc[7] += f.y;
}

__global__ void __launch_bounds__(256) agg_k(float* __restrict__ outb, int N) {
    int warp = (blockIdx.x * blockDim.x + threadIdx.x) >> 5;
    int lane = threadIdx.x & 31;
    if (warp >= N) return;
    int q = lane & 7;
    int g = lane >> 3;

    const char* __restrict__ hbase = reinterpret_cast<const char*>(g_A) + q * 16;
    const int*  __restrict__ row   = g_csr + (size_t)warp * CAP;
    int cnt = g_cnt[warp];
    if (cnt > CAP) cnt = CAP;

    float acc[8] = {0, 0, 0, 0, 0, 0, 0, 0};

    // self-loop row: group 0 only
    if (g == 0) {
        uint4 v = *reinterpret_cast<const uint4*>(hbase + (size_t)warp * 128);
        addf32_u4(acc, v);
    }

    // padded main loop: 16 edges / iteration, no masks
    for (int b = 0; b < cnt; b += 16) {
        int4 idx = *reinterpret_cast<const int4*>(row + b + 4 * g);
        uint4 v0 = *reinterpret_cast<const uint4*>(hbase + idx.x);
        uint4 v1 = *reinterpret_cast<const uint4*>(hbase + idx.y);
        uint4 v2 = *reinterpret_cast<const uint4*>(hbase + idx.z);
        uint4 v3 = *reinterpret_cast<const uint4*>(hbase + idx.w);
        uint4 t = hadd2_u4(hadd2_u4(v0, v1), hadd2_u4(v2, v3));
        addf32_u4(acc, t);
    }

    // fold the 4 groups
    #pragma unroll
    for (int i = 0; i < 8; i++) {
        acc[i] += __shfl_xor_sync(0xffffffffu, acc[i], 8);
        acc[i] += __shfl_xor_sync(0xffffffffu, acc[i], 16);
    }

    float di = rsqrtf((float)g_cnt[warp] + 1.0f);
    if (g < 2) {
        float4 w = make_float4(acc[g * 4 + 0] * di, acc[g * 4 + 1] * di,
                               acc[g * 4 + 2] * di, acc[g * 4 + 3] * di);
        *reinterpret_cast<float4*>(outb + (size_t)warp * 64 + q * 8 + g * 4) = w;
    }
}

// ---------------------------------------------------------------------------
// launch
// ---------------------------------------------------------------------------
extern "C" void kernel_launch(void* const* d_in, const int* in_sizes, int n_in,
                              void* d_out, int out_size) {
    const float* x  = (const float*)d_in[0];
    const int*   ei = (const int*)d_in[1];
    const float* W1 = (const float*)d_in[2];
    const float* b1 = (const float*)d_in[3];
    const float* W2 = (const float*)d_in[4];
    const float* b2 = (const float*)d_in[5];
    const float* Wf = (const float*)d_in[6];
    const float* bf = (const float*)d_in[7];
    float* out = (float*)d_out;

    const int N = in_sizes[0] / 64;
    const int E = in_sizes[1] / 2;

    __half* pA = nullptr;
    float*  pB = nullptr;
    cudaGetSymbolAddress((void**)&pA, g_A);
    cudaGetSymbolAddress((void**)&pB, g_B);

    const int T = 256;
    dim3 bn((N + T - 1) / T), be((E + T - 1) / T);
    dim3 bg((N + 63) / 64);
    dim3 bagg((N * 32 + T - 1) / T);

    zero_k<<<bn, T>>>(N);
    fill_k<<<be, T>>>(ei, E, N);
    pad_k<<<bn, T>>>(N);

    gemm64_k<64, false, false, true, __half><<<bg, T>>>(x, W1, nullptr, nullptr, pA, N);
    agg_k<<<bagg, T>>>(pB, N);

    gemm64_k<64, true, false, true, __half><<<bg, T>>>(pB, W2, b1, nullptr, pA, N);
    agg_k<<<bagg, T>>>(pB, N);

    gemm64_k<32, true, true, false, float><<<bg, T>>>(pB, Wf, b2, bf, out, N);
}

// round 10
// speedup vs baseline: 1.1814x; 1.1355x over previous
#include <cuda_runtime.h>
#include <cuda_fp16.h>
#include <cstdint>

#define MAXN 100000
#define CAP 128            // per-node CSR bucket capacity, multiple of 16
#define ZOFF (MAXN << 7)   // byte offset of the permanently-zero h' row

// Scratch (__device__ globals; allocation-free rule)
// g_A has one extra row (index MAXN): BSS-zeroed, never written -> stays zero.
__device__ __align__(16) __half g_A[(MAXN + 1) * 64];
__device__ __align__(16) float  g_B[MAXN * 64];
__device__ int g_cnt[MAXN];
__device__ __align__(16) int g_csr[MAXN * CAP];  // src row BYTE offsets (s<<7)

// ---------------------------------------------------------------------------
// prep
// ---------------------------------------------------------------------------
__global__ void zero_k(int N) {
    int i = blockIdx.x * blockDim.x + threadIdx.x;
    if (i < N) g_cnt[i] = 0;
}

__global__ void fill_k(const int* __restrict__ ei, int E, int N) {
    int e = blockIdx.x * blockDim.x + threadIdx.x;
    if (e >= E) return;
    int s = __ldg(ei + e);
    int d = __ldg(ei + (size_t)E + e);
    if ((unsigned)s >= (unsigned)N) s = 0;
    if ((unsigned)d >= (unsigned)N) d = 0;
    int pos = atomicAdd(&g_cnt[d], 1);
    if (pos < CAP) g_csr[(size_t)d * CAP + pos] = s << 7;
}

__global__ void pad_k(int N) {
    int i = blockIdx.x * blockDim.x + threadIdx.x;
    if (i >= N) return;
    int c = g_cnt[i];
    if (c > CAP) c = CAP;
    int end = (c + 15) & ~15;
    int* row = g_csr + (size_t)i * CAP;
    for (int j = c; j < end; j++) row[j] = ZOFF;
}

// ---------------------------------------------------------------------------
// tf32 helpers
// ---------------------------------------------------------------------------
__device__ __forceinline__ unsigned f2tf32(float f) {
    unsigned r;
    asm("cvt.rna.tf32.f32 %0, %1;" : "=r"(r) : "f"(f));
    return r;
}

__device__ __forceinline__ void mma_tf32(float* c, unsigned a0, unsigned a1,
                                         unsigned a2, unsigned a3,
                                         unsigned b0, unsigned b1) {
    asm volatile(
        "mma.sync.aligned.m16n8k8.row.col.f32.tf32.tf32.f32 "
        "{%0,%1,%2,%3}, {%4,%5,%6,%7}, {%8,%9}, {%0,%1,%2,%3};"
        : "+f"(c[0]), "+f"(c[1]), "+f"(c[2]), "+f"(c[3])
        : "r"(a0), "r"(a1), "r"(a2), "r"(a3), "r"(b0), "r"(b1));
}

// ---------------------------------------------------------------------------
// Layer GEMM (tensor): out[N,64] = (f(in[N,64]) @ W[64,64]) * dinv[row], fp16.
// Block 128 thr / 4 warps, tile 64 rows. m16n8k8 tf32 MMA, conflict-free
// fragment banking (xs stride 68 -> bank 4*gid+tig; Wsh stride 72 -> 8*tig+gid).
// ---------------------------------------------------------------------------
template <bool PRE>
__global__ void __launch_bounds__(128) gemm_mma_k(
        const float* __restrict__ in, const float* __restrict__ W,
        const float* __restrict__ preb, __half* __restrict__ out, int N) {
    __shared__ unsigned xs[64][68];
    __shared__ unsigned Wsh[64][72];

    const int t = threadIdx.x;
    const int row0 = blockIdx.x * 64;

    #pragma unroll
    for (int i = t; i < 64 * 64; i += 128)
        Wsh[i >> 6][i & 63] = f2tf32(W[i]);

    #pragma unroll
    for (int i = t; i < 64 * 64; i += 128) {
        int r = i >> 6, c = i & 63;
        int gr = row0 + r;
        float v = (gr < N) ? in[(size_t)gr * 64 + c] : 0.0f;
        if (PRE) v = fmaxf(v + preb[c], 0.0f);
        xs[r][c] = f2tf32(v);
    }
    __syncthreads();

    const int lane = t & 31;
    const int gid = lane >> 2;      // 0..7
    const int tig = lane & 3;       // 0..3
    const int wr  = (t >> 5) * 16;  // warp row base in tile

    float acc[8][4];
    #pragma unroll
    for (int ng = 0; ng < 8; ng++)
        #pragma unroll
        for (int j = 0; j < 4; j++) acc[ng][j] = 0.0f;

    #pragma unroll
    for (int k0 = 0; k0 < 64; k0 += 8) {
        unsigned a0 = xs[wr + gid][k0 + tig];
        unsigned a1 = xs[wr + gid + 8][k0 + tig];
        unsigned a2 = xs[wr + gid][k0 + tig + 4];
        unsigned a3 = xs[wr + gid + 8][k0 + tig + 4];
        #pragma unroll
        for (int ng = 0; ng < 8; ng++) {
            unsigned b0 = Wsh[k0 + tig][ng * 8 + gid];
            unsigned b1 = Wsh[k0 + tig + 4][ng * 8 + gid];
            mma_tf32(acc[ng], a0, a1, a2, a3, b0, b1);
        }
    }

    int r1 = row0 + wr + gid;
    int r2 = r1 + 8;
    float sc1 = (r1 < N) ? rsqrtf((float)g_cnt[r1] + 1.0f) : 0.0f;
    float sc2 = (r2 < N) ? rsqrtf((float)g_cnt[r2] + 1.0f) : 0.0f;

    #pragma unroll
    for (int ng = 0; ng < 8; ng++) {
        int col = ng * 8 + 2 * tig;
        if (r1 < N)
            *reinterpret_cast<__half2*>(out + (size_t)r1 * 64 + col) =
                __floats2half2_rn(acc[ng][0] * sc1, acc[ng][1] * sc1);
        if (r2 < N)
            *reinterpret_cast<__half2*>(out + (size_t)r2 * 64 + col) =
                __floats2half2_rn(acc[ng][2] * sc2, acc[ng][3] * sc2);
    }
}

// ---------------------------------------------------------------------------
// Head GEMM (fp32 FFMA): out[N,32] = relu(in + preb) @ Wf + postb
// ---------------------------------------------------------------------------
__global__ void __launch_bounds__(256) gemm_head_k(
        const float* __restrict__ in, const float* __restrict__ W,
        const float* __restrict__ preb, const float* __restrict__ postb,
        float* __restrict__ out, int N) {
    constexpr int NOUT = 32, CPT = 2;
    __shared__ float xs[64][65];
    __shared__ __align__(16) float Ws[64 * NOUT];

    const int t = threadIdx.x;
    const int row0 = blockIdx.x * 64;

    #pragma unroll
    for (int i = t; i < 64 * NOUT; i += 256) Ws[i] = W[i];

    #pragma unroll
    for (int i = 0; i < 16; i++) {
        int lin = t + i * 256;
        int r = lin >> 6, c = lin & 63;
        int gr = row0 + r;
        float v = (gr < N) ? in[(size_t)gr * 64 + c] : 0.0f;
        v = fmaxf(v + preb[c], 0.0f);
        xs[r][c] = v;
    }
    __syncthreads();

    const int r0 = (t >> 4) * 4;
    const int c0 = (t & 15) * CPT;

    float acc[4][CPT];
    #pragma unroll
    for (int i = 0; i < 4; i++)
        #pragma unroll
        for (int j = 0; j < CPT; j++) acc[i][j] = 0.0f;

    #pragma unroll
    for (int k = 0; k < 64; k++) {
        float wv[CPT];
        #pragma unroll
        for (int j = 0; j < CPT; j++) wv[j] = Ws[k * NOUT + c0 + j];
        #pragma unroll
        for (int i = 0; i < 4; i++) {
            float a = xs[r0 + i][k];
            #pragma unroll
            for (int j = 0; j < CPT; j++)
                acc[i][j] = fmaf(a, wv[j], acc[i][j]);
        }
    }

    #pragma unroll
    for (int i = 0; i < 4; i++) {
        int gr = row0 + r0 + i;
        if (gr < N) {
            #pragma unroll
            for (int j = 0; j < CPT; j++)
                out[(size_t)gr * NOUT + c0 + j] = acc[i][j] + postb[c0 + j];
        }
    }
}

// ---------------------------------------------------------------------------
// Aggregation: warp per node, quarter-warp gathers, fp16 4-edge tree.
// ---------------------------------------------------------------------------
__device__ __forceinline__ uint4 hadd2_u4(uint4 a, uint4 b) {
    uint4 r;
    *reinterpret_cast<__half2*>(&r.x) = __hadd2(*reinterpret_cast<__half2*>(&a.x),
                                                *reinterpret_cast<__half2*>(&b.x));
    *reinterpret_cast<__half2*>(&r.y) = __hadd2(*reinterpret_cast<__half2*>(&a.y),
                                                *reinterpret_cast<__half2*>(&b.y));
    *reinterpret_cast<__half2*>(&r.z) = __hadd2(*reinterpret_cast<__half2*>(&a.z),
                                                *reinterpret_cast<__half2*>(&b.z));
    *reinterpret_cast<__half2*>(&r.w) = __hadd2(*reinterpret_cast<__half2*>(&a.w),
                                                *reinterpret_cast<__half2*>(&b.w));
    return r;
}

__device__ __forceinline__ void addf32_u4(float* acc, uint4 v) {
    float2 f;
    f = __half22float2(*reinterpret_cast<__half2*>(&v.x)); acc[0] += f.x; acc[1] += f.y;
    f = __half22float2(*reinterpret_cast<__half2*>(&v.y)); acc[2] += f.x; acc[3] += f.y;
    f = __half22float2(*reinterpret_cast<__half2*>(&v.z)); acc[4] += f.x; acc[5] += f.y;
    f = __half22float2(*reinterpret_cast<__half2*>(&v.w)); acc[6] += f.x; acc[7] += f.y;
}

__global__ void __launch_bounds__(256) agg_k(float* __restrict__ outb, int N) {
    int warp = (blockIdx.x * blockDim.x + threadIdx.x) >> 5;
    int lane = threadIdx.x & 31;
    if (warp >= N) return;
    int q = lane & 7;
    int g = lane >> 3;

    const char* __restrict__ hbase = reinterpret_cast<const char*>(g_A) + q * 16;
    const int*  __restrict__ row   = g_csr + (size_t)warp * CAP;
    int cnt = g_cnt[warp];
    if (cnt > CAP) cnt = CAP;

    float acc[8] = {0, 0, 0, 0, 0, 0, 0, 0};

    if (g == 0) {
        uint4 v = *reinterpret_cast<const uint4*>(hbase + (size_t)warp * 128);
        addf32_u4(acc, v);
    }

    for (int b = 0; b < cnt; b += 16) {
        int4 idx = *reinterpret_cast<const int4*>(row + b + 4 * g);
        uint4 v0 = *reinterpret_cast<const uint4*>(hbase + idx.x);
        uint4 v1 = *reinterpret_cast<const uint4*>(hbase + idx.y);
        uint4 v2 = *reinterpret_cast<const uint4*>(hbase + idx.z);
        uint4 v3 = *reinterpret_cast<const uint4*>(hbase + idx.w);
        uint4 t = hadd2_u4(hadd2_u4(v0, v1), hadd2_u4(v2, v3));
        addf32_u4(acc, t);
    }

    #pragma unroll
    for (int i = 0; i < 8; i++) {
        acc[i] += __shfl_xor_sync(0xffffffffu, acc[i], 8);
        acc[i] += __shfl_xor_sync(0xffffffffu, acc[i], 16);
    }

    float di = rsqrtf((float)g_cnt[warp] + 1.0f);
    if (g < 2) {
        float4 w = make_float4(acc[g * 4 + 0] * di, acc[g * 4 + 1] * di,
                               acc[g * 4 + 2] * di, acc[g * 4 + 3] * di);
        *reinterpret_cast<float4*>(outb + (size_t)warp * 64 + q * 8 + g * 4) = w;
    }
}

// ---------------------------------------------------------------------------
// launch
// ---------------------------------------------------------------------------
extern "C" void kernel_launch(void* const* d_in, const int* in_sizes, int n_in,
                              void* d_out, int out_size) {
    const float* x  = (const float*)d_in[0];
    const int*   ei = (const int*)d_in[1];
    const float* W1 = (const float*)d_in[2];
    const float* b1 = (const float*)d_in[3];
    const float* W2 = (const float*)d_in[4];
    const float* b2 = (const float*)d_in[5];
    const float* Wf = (const float*)d_in[6];
    const float* bf = (const float*)d_in[7];
    float* out = (float*)d_out;

    const int N = in_sizes[0] / 64;
    const int E = in_sizes[1] / 2;

    __half* pA = nullptr;
    float*  pB = nullptr;
    cudaGetSymbolAddress((void**)&pA, g_A);
    cudaGetSymbolAddress((void**)&pB, g_B);

    const int T = 256;
    dim3 bn((N + T - 1) / T), be((E + T - 1) / T);
    dim3 bg((N + 63) / 64);
    dim3 bagg((N * 32 + T - 1) / T);

    zero_k<<<bn, T>>>(N);
    fill_k<<<be, T>>>(ei, E, N);
    pad_k<<<bn, T>>>(N);

    // layer 1: h' = (x @ W1) * dinv (tf32 MMA -> fp16); agg -> fp32
    gemm_mma_k<false><<<bg, 128>>>(x, W1, nullptr, pA, N);
    agg_k<<<bagg, T>>>(pB, N);

    // layer 2: h' = (relu(agg1 + b1) @ W2) * dinv (tf32 MMA -> fp16); agg
    gemm_mma_k<true><<<bg, 128>>>(pB, W2, b1, pA, N);
    agg_k<<<bagg, T>>>(pB, N);

    // head: out = relu(agg2 + b2) @ Wf + bf (fp32 FFMA)
    gemm_head_k<<<bg, T>>>(pB, Wf, b2, bf, out, N);
}